// round 1
// baseline (speedup 1.0000x reference)
#include <cuda_runtime.h>

#define NSTEPS  100
#define SAMP    64
#define THREADS 256
#define HID     64
#define MAXBLK  4096

struct Smem {
    float wt[3][HID][HID];       // wt[l][k][j] = W_{l+1}[j][k]  (transposed)
    float hv[HID][2 * SAMP];     // interleaved (h, v) pairs: hv[k][2s]=h, hv[k][2s+1]=v
    float w0t[HID], w0y[HID], b0v[HID];
    float bl[3][HID];
    float w4[HID];
    float y_s[SAMP];
    float red[SAMP];
    float b4v;
};

__device__ float g_partials[MAXBLK];

// Packed f32x2 FMA (Blackwell): two independent fp32 FMAs per instruction.
__device__ __forceinline__ unsigned long long ffma2(unsigned long long a,
                                                    unsigned long long b,
                                                    unsigned long long c) {
    unsigned long long d;
    asm("fma.rn.f32x2 %0, %1, %2, %3;" : "=l"(d) : "l"(a), "l"(b), "l"(c));
    return d;
}
__device__ __forceinline__ unsigned long long pack2(float x, float y) {
    unsigned long long d;
    asm("mov.b64 %0, {%1, %2};" : "=l"(d) : "f"(x), "f"(y));
    return d;
}
__device__ __forceinline__ void unpack2(unsigned long long d, float &x, float &y) {
    asm("mov.b64 {%0, %1}, %2;" : "=f"(x), "=f"(y) : "l"(d));
}

__global__ void __launch_bounds__(THREADS, 2) fbsnn_kernel(
    const float *__restrict__ W0, const float *__restrict__ b0,
    const float *__restrict__ W1, const float *__restrict__ b1,
    const float *__restrict__ W2, const float *__restrict__ b2,
    const float *__restrict__ W3, const float *__restrict__ b3,
    const float *__restrict__ W4, const float *__restrict__ b4,
    const float *__restrict__ y0p, const float *__restrict__ dW, int B)
{
    extern __shared__ float smem_raw[];
    Smem &S = *reinterpret_cast<Smem *>(smem_raw);
    const int tid = threadIdx.x;

    // ---- cooperative weight load (transposed hidden layers) ----
    {
        const float *Wl[3] = {W1, W2, W3};
        #pragma unroll 1
        for (int l = 0; l < 3; l++)
            for (int idx = tid; idx < HID * HID; idx += THREADS) {
                int j = idx >> 6, k = idx & 63;
                S.wt[l][k][j] = Wl[l][idx];
            }
        for (int idx = tid; idx < HID; idx += THREADS) {
            S.w0t[idx] = W0[2 * idx];
            S.w0y[idx] = W0[2 * idx + 1];
            S.b0v[idx] = b0[idx];
            S.bl[0][idx] = b1[idx];
            S.bl[1][idx] = b2[idx];
            S.bl[2][idx] = b3[idx];
            S.w4[idx]  = W4[idx];
        }
        if (tid == 0) S.b4v = b4[0];
    }

    const int ts = tid & 15, tj = tid >> 4;
    const int s0 = ts * 4, j0 = tj * 4;

    const float dt = 0.01f;
    const float sqrt_dt = sqrtf(0.01f);   // matches np.float32(0.01)**0.5

    float y = 0.f, Yc = 0.f, Dc = 0.f, loss = 0.f, Ytil = 0.f;
    if (tid < SAMP) {
        y = y0p[0];
        S.y_s[tid] = y;
    }
    float t = 0.f;
    const long gs = (long)blockIdx.x * SAMP + tid;   // valid for tid < SAMP

    for (int n = 0; n <= NSTEPS; n++) {
        // =================== network eval at (t, y_s) ===================
        __syncthreads();   // y_s (and weights, first iter) visible; prior hv reads done

        // ---- layer 0: x = (t, y), tangent input (0, 1) ----
        {
            float yv[4];
            *(float4 *)yv = *(const float4 *)&S.y_s[s0];
            #pragma unroll
            for (int ji = 0; ji < 4; ji++) {
                const int j = j0 + ji;
                const float wt_ = S.w0t[j], wy = S.w0y[j], bb = S.b0v[j];
                float o[8];
                #pragma unroll
                for (int si = 0; si < 4; si++) {
                    float z = fmaf(wt_, t, fmaf(wy, yv[si], bb));
                    o[2 * si]     = __sinf(z);
                    o[2 * si + 1] = __cosf(z) * wy;
                }
                *(float4 *)&S.hv[j][2 * s0]     = *(float4 *)&o[0];
                *(float4 *)&S.hv[j][2 * s0 + 4] = *(float4 *)&o[4];
            }
        }
        __syncthreads();

        // ---- hidden layers 1..3: z = W h + b, u = W v; h'=sin z, v'=cos z * u ----
        #pragma unroll 1
        for (int l = 0; l < 3; l++) {
            unsigned long long acc[4][4];   // [ji][si], lo = z-acc, hi = u-acc
            #pragma unroll
            for (int ji = 0; ji < 4; ji++)
                #pragma unroll
                for (int si = 0; si < 4; si++) acc[ji][si] = 0ull;

            #pragma unroll 4
            for (int k = 0; k < HID; k++) {
                ulonglong2 p01 = *(const ulonglong2 *)&S.hv[k][2 * s0];
                ulonglong2 p23 = *(const ulonglong2 *)&S.hv[k][2 * s0 + 4];
                float4 wk = *(const float4 *)&S.wt[l][k][j0];
                unsigned long long hvp[4] = {p01.x, p01.y, p23.x, p23.y};
                unsigned long long wp[4] = {pack2(wk.x, wk.x), pack2(wk.y, wk.y),
                                            pack2(wk.z, wk.z), pack2(wk.w, wk.w)};
                #pragma unroll
                for (int ji = 0; ji < 4; ji++)
                    #pragma unroll
                    for (int si = 0; si < 4; si++)
                        acc[ji][si] = ffma2(wp[ji], hvp[si], acc[ji][si]);
            }
            __syncthreads();   // all reads of hv done before in-place overwrite
            #pragma unroll
            for (int ji = 0; ji < 4; ji++) {
                const int j = j0 + ji;
                const float bb = S.bl[l][j];
                float o[8];
                #pragma unroll
                for (int si = 0; si < 4; si++) {
                    float zz, uu;
                    unpack2(acc[ji][si], zz, uu);
                    zz += bb;
                    o[2 * si]     = __sinf(zz);
                    o[2 * si + 1] = __cosf(zz) * uu;
                }
                *(float4 *)&S.hv[j][2 * s0]     = *(float4 *)&o[0];
                *(float4 *)&S.hv[j][2 * s0 + 4] = *(float4 *)&o[4];
            }
            __syncthreads();
        }

        // ---- output layer + Euler-Maruyama step (one thread per sample) ----
        if (tid < SAMP) {
            float Ya = S.b4v, Da = 0.f;
            #pragma unroll 8
            for (int k = 0; k < HID; k++) {
                float2 p = *(const float2 *)&S.hv[k][2 * tid];
                const float w = S.w4[k];
                Ya = fmaf(w, p.x, Ya);
                Da = fmaf(w, p.y, Da);
            }
            if (n > 0) {
                float d = Ya - Ytil;
                loss = fmaf(d, d, loss);
            }
            Yc = Ya;
            Dc = Da;
            if (n < NSTEPS) {
                float Z0 = 0.5f * Dc;      // sigma * dY
                float q0 = -Dc;            // -0.5*Z0/sigma^2, exact (powers of 2)
                float dws = dW[(long)n * B + gs] * sqrt_dt;
                float y1 = y + q0 * dt + 0.5f * dws;
                Ytil = Yc - (q0 * q0) * dt + Z0 * dws;
                y = y1;
                S.y_s[tid] = y1;
            }
        }
        t += dt;   // fp32 accumulation, matches scan carry
    }

    // ---- terminal costs ----
    if (tid < SAMP) {
        float e1 = Yc - y * y;        // Y_N - alpha*y^2
        float e2 = Dc - 2.f * y;      // dY_N - 2*alpha*y
        loss = fmaf(e1, e1, fmaf(e2, e2, loss));
        S.red[tid] = loss;
    }
    __syncthreads();
    if (tid == 0) {
        float s = 0.f;
        #pragma unroll 8
        for (int i = 0; i < SAMP; i++) s += S.red[i];
        g_partials[blockIdx.x] = s;
    }
}

__global__ void reduce_kernel(float *out, int nblocks, float invB) {
    __shared__ float sh[256];
    float s = 0.f;
    for (int i = threadIdx.x; i < nblocks; i += 256) s += g_partials[i];
    sh[threadIdx.x] = s;
    __syncthreads();
    for (int off = 128; off > 0; off >>= 1) {
        if (threadIdx.x < off) sh[threadIdx.x] += sh[threadIdx.x + off];
        __syncthreads();
    }
    if (threadIdx.x == 0) out[0] = sh[0] * invB;
}

extern "C" void kernel_launch(void* const* d_in, const int* in_sizes, int n_in,
                              void* d_out, int out_size) {
    const float *W0  = (const float *)d_in[0];
    const float *b0  = (const float *)d_in[1];
    const float *W1  = (const float *)d_in[2];
    const float *b1  = (const float *)d_in[3];
    const float *W2  = (const float *)d_in[4];
    const float *b2  = (const float *)d_in[5];
    const float *W3  = (const float *)d_in[6];
    const float *b3  = (const float *)d_in[7];
    const float *W4  = (const float *)d_in[8];
    const float *b4  = (const float *)d_in[9];
    const float *y0p = (const float *)d_in[10];
    const float *dW  = (const float *)d_in[11];

    const int B = in_sizes[11] / NSTEPS;
    const int nblocks = B / SAMP;

    cudaFuncSetAttribute(fbsnn_kernel,
                         cudaFuncAttributeMaxDynamicSharedMemorySize,
                         (int)sizeof(Smem));

    fbsnn_kernel<<<nblocks, THREADS, sizeof(Smem)>>>(
        W0, b0, W1, b1, W2, b2, W3, b3, W4, b4, y0p, dW, B);
    reduce_kernel<<<1, 256>>>((float *)d_out, nblocks, 1.0f / (float)B);
}

// round 3
// speedup vs baseline: 3.3095x; 3.3095x over previous
#include <cuda_runtime.h>
#include <cuda_fp16.h>
#include <cstdint>

#define NSTEPS  100
#define SAMP    64
#define THREADS 256
#define HID     64
#define MAXBLK  4096

// BL[layer][wpart][kt][nt][lane] -> uint2 (b0,b1 f16x2 fragments)
struct Smem {
    unsigned int BL[3][2][4][8][32][2];   // 49152 B
    float w0t[HID], w0y[HID], b0v[HID];
    float bl[3][HID];
    float w4[HID];
    float y_s[SAMP];
    float part[128];
    float red[SAMP];
    float b4v;
};

__device__ float g_partials[MAXBLK];

__device__ __forceinline__ void mma16816(float* d, const unsigned* a, const unsigned* b) {
    asm volatile(
        "mma.sync.aligned.m16n8k16.row.col.f32.f16.f16.f32 "
        "{%0,%1,%2,%3}, {%4,%5,%6,%7}, {%8,%9}, {%0,%1,%2,%3};"
        : "+f"(d[0]), "+f"(d[1]), "+f"(d[2]), "+f"(d[3])
        : "r"(a[0]), "r"(a[1]), "r"(a[2]), "r"(a[3]), "r"(b[0]), "r"(b[1]));
}

// split two fp32 values into (hi, lo) fp16 parts, packed as f16x2 (x -> low half)
__device__ __forceinline__ void split_pack(float x, float y,
                                           unsigned &u0, unsigned &u1) {
    __half xa = __float2half_rn(x), ya = __float2half_rn(y);
    float xr = x - __half2float(xa), yr = y - __half2float(ya);
    __half xb = __float2half_rn(xr), yb = __float2half_rn(yr);
    __half2 p0 = __halves2half2(xa, ya);
    __half2 p1 = __halves2half2(xb, yb);
    u0 = *reinterpret_cast<unsigned*>(&p0);
    u1 = *reinterpret_cast<unsigned*>(&p1);
}

__global__ void nop_kernel() {}

__global__ void __launch_bounds__(THREADS, 2) fbsnn_kernel(
    const float *__restrict__ W0, const float *__restrict__ b0,
    const float *__restrict__ W1, const float *__restrict__ b1,
    const float *__restrict__ W2, const float *__restrict__ b2,
    const float *__restrict__ W3, const float *__restrict__ b3,
    const float *__restrict__ W4, const float *__restrict__ b4,
    const float *__restrict__ y0p, const float *__restrict__ dW, int B)
{
    extern __shared__ unsigned char smem_raw[];
    Smem *S = reinterpret_cast<Smem *>(smem_raw);

    const int tid  = threadIdx.x;
    const int wid  = tid >> 5;
    const int lane = tid & 31;
    const int g    = lane >> 2;       // fragment group (row within tile)
    const int q    = lane & 3;        // quad (col pair)
    const int row_lo = 16 * wid + g;  // global M row (0..127): 2s+parity
    const int row_hi = row_lo + 8;
    const bool is_h = ((g & 1) == 0); // even rows = forward chain, odd = tangent

    // ---------------- one-time init: weight fragment tables ----------------
    {
        const float *Wl[3] = {W1, W2, W3};
        for (int idx = tid; idx < 3 * 4 * 8 * 32; idx += THREADS) {
            int ln = idx & 31;
            int nt = (idx >> 5) & 7;
            int kt = (idx >> 8) & 3;
            int l  = idx >> 10;
            int gg = ln >> 2, qq = ln & 3;
            int j  = nt * 8 + gg;            // output unit (N index)
            int k0 = kt * 16 + 2 * qq;       // K index base
            const float *Wp = Wl[l] + j * HID;
            float w00 = Wp[k0],     w01 = Wp[k0 + 1];
            float w08 = Wp[k0 + 8], w09 = Wp[k0 + 9];
            unsigned a0, a1, b0_, b1_;
            split_pack(w00, w01, a0, a1);
            split_pack(w08, w09, b0_, b1_);
            S->BL[l][0][kt][nt][ln][0] = a0;   // part0: b0 (k 2q,2q+1)
            S->BL[l][0][kt][nt][ln][1] = b0_;  // part0: b1 (k 2q+8,2q+9)
            S->BL[l][1][kt][nt][ln][0] = a1;   // part1
            S->BL[l][1][kt][nt][ln][1] = b1_;
        }
        for (int idx = tid; idx < HID; idx += THREADS) {
            S->w0t[idx] = W0[2 * idx];
            S->w0y[idx] = W0[2 * idx + 1];
            S->b0v[idx] = b0[idx];
            S->bl[0][idx] = b1[idx];
            S->bl[1][idx] = b2[idx];
            S->bl[2][idx] = b3[idx];
            S->w4[idx]  = W4[idx];
        }
        if (tid == 0) S->b4v = b4[0];
    }

    const float dt = 0.01f;
    const float sqrt_dt = sqrtf(0.01f);   // matches np.float32(0.01)**0.5

    float y = 0.f, Yc = 0.f, Dc = 0.f, loss = 0.f, Ytil = 0.f;
    if (tid < SAMP) {
        y = y0p[0];
        S->y_s[tid] = y;
    }
    float t = 0.f;
    const long gs = (long)blockIdx.x * SAMP + tid;

    for (int n = 0; n <= NSTEPS; n++) {
        __syncthreads();   // y_s ready (and init tables on first iter)

        unsigned A0[4][4], A1[4][4];   // fp16x2 A fragments, hi/lo split parts

        // ---------- layer 0: build A fragments from (t, y) ----------
        {
            const float y_lo = S->y_s[row_lo >> 1];
            const float y_hi = S->y_s[row_hi >> 1];
#pragma unroll
            for (int nt = 0; nt < 8; nt++) {
#pragma unroll
                for (int rh = 0; rh < 2; rh++) {
                    const float yv = rh ? y_hi : y_lo;
                    float act[2];
#pragma unroll
                    for (int e = 0; e < 2; e++) {
                        const int j = nt * 8 + 2 * q + e;
                        const float wy = S->w0y[j];
                        float z = fmaf(S->w0t[j], t, fmaf(wy, yv, S->b0v[j]));
                        act[e] = is_h ? __sinf(z) : (__cosf(z) * wy);
                    }
                    const int kt = nt >> 1, r = (nt & 1) * 2 + rh;
                    split_pack(act[0], act[1], A0[kt][r], A1[kt][r]);
                }
            }
        }

        // ---------- hidden layers 1..3 (register-resident pipeline) ----------
#pragma unroll
        for (int l = 0; l < 3; l++) {
            float d[8][4];
#pragma unroll
            for (int nt = 0; nt < 8; nt++)
#pragma unroll
                for (int i = 0; i < 4; i++) d[nt][i] = 0.f;

#pragma unroll
            for (int wp = 0; wp < 2; wp++) {
                const uint2 *bp = reinterpret_cast<const uint2 *>(
                    &S->BL[l][wp][0][0][0][0]);
#pragma unroll
                for (int kt = 0; kt < 4; kt++) {
                    uint2 bfrag[8];
#pragma unroll
                    for (int nt = 0; nt < 8; nt++)
                        bfrag[nt] = bp[(kt * 8 + nt) * 32 + lane];
#pragma unroll
                    for (int nt = 0; nt < 8; nt++)
                        mma16816(d[nt], A0[kt], reinterpret_cast<unsigned*>(&bfrag[nt]));
#pragma unroll
                    for (int nt = 0; nt < 8; nt++)
                        mma16816(d[nt], A1[kt], reinterpret_cast<unsigned*>(&bfrag[nt]));
                }
            }

            if (l < 2) {
                // mid epilogue: bias + pair-shuffle + sin/cos + fp16 split
#pragma unroll
                for (int nt = 0; nt < 8; nt++) {
#pragma unroll
                    for (int rh = 0; rh < 2; rh++) {
                        float act[2];
#pragma unroll
                        for (int e = 0; e < 2; e++) {
                            const int j = nt * 8 + 2 * q + e;
                            float val = d[nt][2 * rh + e];
                            float tmp = is_h ? (val + S->bl[l][j]) : val;
                            float zb = __shfl_xor_sync(0xffffffffu, tmp, 4);
                            act[e] = is_h ? __sinf(tmp) : (__cosf(zb) * val);
                        }
                        const int kt = nt >> 1, r = (nt & 1) * 2 + rh;
                        split_pack(act[0], act[1], A0[kt][r], A1[kt][r]);
                    }
                }
            } else {
                // final epilogue: activation + fold W4 dot-product
                float acc_lo = 0.f, acc_hi = 0.f;
#pragma unroll
                for (int nt = 0; nt < 8; nt++) {
#pragma unroll
                    for (int rh = 0; rh < 2; rh++) {
                        float a = 0.f;
#pragma unroll
                        for (int e = 0; e < 2; e++) {
                            const int j = nt * 8 + 2 * q + e;
                            float val = d[nt][2 * rh + e];
                            float tmp = is_h ? (val + S->bl[2][j]) : val;
                            float zb = __shfl_xor_sync(0xffffffffu, tmp, 4);
                            float act = is_h ? __sinf(tmp) : (__cosf(zb) * val);
                            a = fmaf(S->w4[j], act, a);
                        }
                        if (rh == 0) acc_lo += a; else acc_hi += a;
                    }
                }
                // reduce over quad q (lanes xor 1, xor 2 share the same rows)
                acc_lo += __shfl_xor_sync(0xffffffffu, acc_lo, 1);
                acc_lo += __shfl_xor_sync(0xffffffffu, acc_lo, 2);
                acc_hi += __shfl_xor_sync(0xffffffffu, acc_hi, 1);
                acc_hi += __shfl_xor_sync(0xffffffffu, acc_hi, 2);
                if (q == 0) {
                    S->part[row_lo] = acc_lo;
                    S->part[row_hi] = acc_hi;
                }
            }
        }
        __syncthreads();   // part[] ready

        // ---------- output + Euler-Maruyama (one thread per sample) ----------
        if (tid < SAMP) {
            float Ya = S->b4v + S->part[2 * tid];      // even row: sum w4*h
            float Da = S->part[2 * tid + 1];           // odd row:  sum w4*v
            if (n > 0) {
                float dd = Ya - Ytil;
                loss = fmaf(dd, dd, loss);
            }
            Yc = Ya;
            Dc = Da;
            if (n < NSTEPS) {
                float Z0 = 0.5f * Dc;
                float q0 = -Dc;
                float dws = dW[(long)n * B + gs] * sqrt_dt;
                float y1 = y + q0 * dt + 0.5f * dws;
                Ytil = Yc - (q0 * q0) * dt + Z0 * dws;
                y = y1;
                S->y_s[tid] = y1;
            }
        }
        t += dt;
    }

    // ---------- terminal costs + block reduction ----------
    if (tid < SAMP) {
        float e1 = Yc - y * y;
        float e2 = Dc - 2.f * y;
        loss = fmaf(e1, e1, fmaf(e2, e2, loss));
        S->red[tid] = loss;
    }
    __syncthreads();
    if (tid == 0) {
        float sum = 0.f;
#pragma unroll 8
        for (int i = 0; i < SAMP; i++) sum += S->red[i];
        g_partials[blockIdx.x] = sum;
    }
}

__global__ void reduce_kernel(float *out, int nblocks, float invB) {
    __shared__ float sh[256];
    float sum = 0.f;
    for (int i = threadIdx.x; i < nblocks; i += 256) sum += g_partials[i];
    sh[threadIdx.x] = sum;
    __syncthreads();
    for (int off = 128; off > 0; off >>= 1) {
        if (threadIdx.x < off) sh[threadIdx.x] += sh[threadIdx.x + off];
        __syncthreads();
    }
    if (threadIdx.x == 0) out[0] = sh[0] * invB;
}

extern "C" void kernel_launch(void* const* d_in, const int* in_sizes, int n_in,
                              void* d_out, int out_size) {
    const float *W0  = (const float *)d_in[0];
    const float *b0  = (const float *)d_in[1];
    const float *W1  = (const float *)d_in[2];
    const float *b1  = (const float *)d_in[3];
    const float *W2  = (const float *)d_in[4];
    const float *b2  = (const float *)d_in[5];
    const float *W3  = (const float *)d_in[6];
    const float *b3  = (const float *)d_in[7];
    const float *W4  = (const float *)d_in[8];
    const float *b4  = (const float *)d_in[9];
    const float *y0p = (const float *)d_in[10];
    const float *dW  = (const float *)d_in[11];

    const int B = in_sizes[11] / NSTEPS;
    const int nblocks = B / SAMP;

    cudaFuncSetAttribute(fbsnn_kernel,
                         cudaFuncAttributeMaxDynamicSharedMemorySize,
                         (int)sizeof(Smem));

    // 4-launch pattern so ncu's fixed "-s 5 -c 1" lands on fbsnn_kernel
    nop_kernel<<<1, 32>>>();
    fbsnn_kernel<<<nblocks, THREADS, sizeof(Smem)>>>(
        W0, b0, W1, b1, W2, b2, W3, b3, W4, b4, y0p, dW, B);
    nop_kernel<<<1, 32>>>();
    reduce_kernel<<<1, 256>>>((float *)d_out, nblocks, 1.0f / (float)B);
}

// round 4
// speedup vs baseline: 3.9742x; 1.2009x over previous
#include <cuda_runtime.h>
#include <cuda_fp16.h>
#include <cstdint>

#define NSTEPS  100
#define SAMP    64
#define THREADS 256
#define HID     64
#define MAXBLK  4096

// BL[layer][wpart][kt][nt][lane] -> uint2 (b0,b1 f16x2 fragments)
struct Smem {
    unsigned int BL[3][2][4][8][32][2];   // 49152 B
    float w0t[HID], w0y[HID], b0v[HID];
    float bl[3][HID];
    float w4[HID];
    float red[SAMP];
    float b4v;
};

__device__ float g_partials[MAXBLK];

__device__ __forceinline__ void mma16816(float* d, const unsigned* a, const unsigned* b) {
    asm volatile(
        "mma.sync.aligned.m16n8k16.row.col.f32.f16.f16.f32 "
        "{%0,%1,%2,%3}, {%4,%5,%6,%7}, {%8,%9}, {%0,%1,%2,%3};"
        : "+f"(d[0]), "+f"(d[1]), "+f"(d[2]), "+f"(d[3])
        : "r"(a[0]), "r"(a[1]), "r"(a[2]), "r"(a[3]), "r"(b[0]), "r"(b[1]));
}

// split two fp32 values into (hi, lo) fp16 parts, packed as f16x2 (x -> low half)
__device__ __forceinline__ void split_pack(float x, float y,
                                           unsigned &u0, unsigned &u1) {
    __half2 p0 = __floats2half2_rn(x, y);
    float2 f = __half22float2(p0);
    __half2 p1 = __floats2half2_rn(x - f.x, y - f.y);
    u0 = *reinterpret_cast<unsigned*>(&p0);
    u1 = *reinterpret_cast<unsigned*>(&p1);
}

__global__ void nop_kernel() {}

__global__ void __launch_bounds__(THREADS, 2) fbsnn_kernel(
    const float *__restrict__ W0, const float *__restrict__ b0,
    const float *__restrict__ W1, const float *__restrict__ b1,
    const float *__restrict__ W2, const float *__restrict__ b2,
    const float *__restrict__ W3, const float *__restrict__ b3,
    const float *__restrict__ W4, const float *__restrict__ b4,
    const float *__restrict__ y0p, const float *__restrict__ dW, int B)
{
    extern __shared__ unsigned char smem_raw[];
    Smem *S = reinterpret_cast<Smem *>(smem_raw);

    const int tid  = threadIdx.x;
    const int wid  = tid >> 5;
    const int lane = tid & 31;
    const int g    = lane >> 2;       // fragment group (row within tile)
    const int q    = lane & 3;        // quad (col pair)
    const int row_lo = 16 * wid + g;  // global M row (0..127)
    const bool is_h = ((g & 1) == 0); // even rows = forward chain, odd = tangent

    // ---------------- one-time init: weight fragment tables ----------------
    {
        const float *Wl[3] = {W1, W2, W3};
        for (int idx = tid; idx < 3 * 4 * 8 * 32; idx += THREADS) {
            int ln = idx & 31;
            int nt = (idx >> 5) & 7;
            int kt = (idx >> 8) & 3;
            int l  = idx >> 10;
            int gg = ln >> 2, qq = ln & 3;
            int j  = nt * 8 + gg;            // output unit (N index)
            int k0 = kt * 16 + 2 * qq;       // K index base
            const float *Wp = Wl[l] + j * HID;
            unsigned a0, a1, c0, c1;
            split_pack(Wp[k0],     Wp[k0 + 1], a0, a1);
            split_pack(Wp[k0 + 8], Wp[k0 + 9], c0, c1);
            S->BL[l][0][kt][nt][ln][0] = a0;   // part0: k 2q,2q+1
            S->BL[l][0][kt][nt][ln][1] = c0;   // part0: k 2q+8,2q+9
            S->BL[l][1][kt][nt][ln][0] = a1;   // part1
            S->BL[l][1][kt][nt][ln][1] = c1;
        }
        for (int idx = tid; idx < HID; idx += THREADS) {
            S->w0t[idx] = W0[2 * idx];
            S->w0y[idx] = W0[2 * idx + 1];
            S->b0v[idx] = b0[idx];
            S->bl[0][idx] = b1[idx];
            S->bl[1][idx] = b2[idx];
            S->bl[2][idx] = b3[idx];
            S->w4[idx]  = W4[idx];
        }
        if (tid == 0) S->b4v = b4[0];
    }
    __syncthreads();   // the ONLY block barrier until the final reduction

    const float dt = 0.01f;
    const float sqrt_dt = sqrtf(0.01f);   // matches np.float32(0.01)**0.5

    // Per-lane sample ownership: this lane's rows are row_lo (sample slo) and
    // row_lo+8 (sample shi). After the q-butterfly + xor4 exchange, every lane
    // holds full (Y, D) for exactly these two samples -> EM step is local.
    const int  slo = 8 * wid + (g >> 1);          // sample of row_lo (block-local)
    const long gs_lo = (long)blockIdx.x * SAMP + slo;
    const long gs_hi = gs_lo + 4;

    float y_lo = y0p[0], y_hi = y_lo;
    float loss_lo = 0.f, loss_hi = 0.f;
    float Ytil_lo = 0.f, Ytil_hi = 0.f;
    float Y_lo = 0.f, D_lo = 0.f, Y_hi = 0.f, D_hi = 0.f;
    float t = 0.f;

    for (int n = 0; n <= NSTEPS; n++) {
        // prefetch this step's noise early; consumed after 4 layers of compute
        float dwn_lo = 0.f, dwn_hi = 0.f;
        if (n < NSTEPS) {
            dwn_lo = dW[(long)n * B + gs_lo];
            dwn_hi = dW[(long)n * B + gs_hi];
        }

        unsigned A0[4][4], A1[4][4];   // fp16x2 A fragments, hi/lo split parts

        // ---------- layer 0: build A fragments from (t, y) ----------
#pragma unroll
        for (int nt = 0; nt < 8; nt++) {
#pragma unroll
            for (int rh = 0; rh < 2; rh++) {
                const float yv = rh ? y_hi : y_lo;
                float act[2];
#pragma unroll
                for (int e = 0; e < 2; e++) {
                    const int j = nt * 8 + 2 * q + e;
                    const float wy = S->w0y[j];
                    float z = fmaf(S->w0t[j], t, fmaf(wy, yv, S->b0v[j]));
                    act[e] = is_h ? __sinf(z) : (__cosf(z) * wy);
                }
                const int kt = nt >> 1, r = (nt & 1) * 2 + rh;
                split_pack(act[0], act[1], A0[kt][r], A1[kt][r]);
            }
        }

        // ---------- hidden layers 1..3 (register-resident, 3-term split) ----------
#pragma unroll
        for (int l = 0; l < 3; l++) {
            float d[8][4];
#pragma unroll
            for (int nt = 0; nt < 8; nt++)
#pragma unroll
                for (int i = 0; i < 4; i++) d[nt][i] = 0.f;

            // pass A0*W0 + A1*W0
            {
                const uint2 *bp = reinterpret_cast<const uint2 *>(
                    &S->BL[l][0][0][0][0][0]);
#pragma unroll
                for (int kt = 0; kt < 4; kt++) {
                    uint2 bfrag[8];
#pragma unroll
                    for (int nt = 0; nt < 8; nt++)
                        bfrag[nt] = bp[(kt * 8 + nt) * 32 + lane];
#pragma unroll
                    for (int nt = 0; nt < 8; nt++)
                        mma16816(d[nt], A0[kt], reinterpret_cast<unsigned*>(&bfrag[nt]));
#pragma unroll
                    for (int nt = 0; nt < 8; nt++)
                        mma16816(d[nt], A1[kt], reinterpret_cast<unsigned*>(&bfrag[nt]));
                }
            }
            // pass A0*W1 (lo x lo dropped: ~2^-22 relative)
            {
                const uint2 *bp = reinterpret_cast<const uint2 *>(
                    &S->BL[l][1][0][0][0][0]);
#pragma unroll
                for (int kt = 0; kt < 4; kt++) {
                    uint2 bfrag[8];
#pragma unroll
                    for (int nt = 0; nt < 8; nt++)
                        bfrag[nt] = bp[(kt * 8 + nt) * 32 + lane];
#pragma unroll
                    for (int nt = 0; nt < 8; nt++)
                        mma16816(d[nt], A0[kt], reinterpret_cast<unsigned*>(&bfrag[nt]));
                }
            }

            if (l < 2) {
                // mid epilogue: bias + pair-shuffle + sin/cos + fp16 split
#pragma unroll
                for (int nt = 0; nt < 8; nt++) {
#pragma unroll
                    for (int rh = 0; rh < 2; rh++) {
                        float act[2];
#pragma unroll
                        for (int e = 0; e < 2; e++) {
                            const int j = nt * 8 + 2 * q + e;
                            float val = d[nt][2 * rh + e];
                            float tmp = is_h ? (val + S->bl[l][j]) : val;
                            float zb = __shfl_xor_sync(0xffffffffu, tmp, 4);
                            act[e] = is_h ? __sinf(tmp) : (__cosf(zb) * val);
                        }
                        const int kt = nt >> 1, r = (nt & 1) * 2 + rh;
                        split_pack(act[0], act[1], A0[kt][r], A1[kt][r]);
                    }
                }
            } else {
                // final epilogue: activation + fold W4 dot-product
                float acc_lo = 0.f, acc_hi = 0.f;
#pragma unroll
                for (int nt = 0; nt < 8; nt++) {
#pragma unroll
                    for (int rh = 0; rh < 2; rh++) {
                        float a = 0.f;
#pragma unroll
                        for (int e = 0; e < 2; e++) {
                            const int j = nt * 8 + 2 * q + e;
                            float val = d[nt][2 * rh + e];
                            float tmp = is_h ? (val + S->bl[2][j]) : val;
                            float zb = __shfl_xor_sync(0xffffffffu, tmp, 4);
                            float act = is_h ? __sinf(tmp) : (__cosf(zb) * val);
                            a = fmaf(S->w4[j], act, a);
                        }
                        if (rh == 0) acc_lo += a; else acc_hi += a;
                    }
                }
                // butterfly over the quad -> every lane holds full row sums
                acc_lo += __shfl_xor_sync(0xffffffffu, acc_lo, 1);
                acc_lo += __shfl_xor_sync(0xffffffffu, acc_lo, 2);
                acc_hi += __shfl_xor_sync(0xffffffffu, acc_hi, 1);
                acc_hi += __shfl_xor_sync(0xffffffffu, acc_hi, 2);
                // exchange h<->v rows (g xor 1 == lane xor 4)
                float oth_lo = __shfl_xor_sync(0xffffffffu, acc_lo, 4);
                float oth_hi = __shfl_xor_sync(0xffffffffu, acc_hi, 4);
                // both lanes of a pair end up with identical (Y, D)
                Y_lo = S->b4v + (is_h ? acc_lo : oth_lo);
                D_lo =          (is_h ? oth_lo : acc_lo);
                Y_hi = S->b4v + (is_h ? acc_hi : oth_hi);
                D_hi =          (is_h ? oth_hi : acc_hi);
            }
        }

        // ---------- Euler-Maruyama step, fully register-resident ----------
        if (n > 0) {
            float d0 = Y_lo - Ytil_lo;
            loss_lo = fmaf(d0, d0, loss_lo);
            float d1 = Y_hi - Ytil_hi;
            loss_hi = fmaf(d1, d1, loss_hi);
        }
        if (n < NSTEPS) {
            {
                float Z0 = 0.5f * D_lo, q0 = -D_lo;
                float dws = dwn_lo * sqrt_dt;
                y_lo = y_lo + q0 * dt + 0.5f * dws;
                Ytil_lo = Y_lo - (q0 * q0) * dt + Z0 * dws;
            }
            {
                float Z0 = 0.5f * D_hi, q0 = -D_hi;
                float dws = dwn_hi * sqrt_dt;
                y_hi = y_hi + q0 * dt + 0.5f * dws;
                Ytil_hi = Y_hi - (q0 * q0) * dt + Z0 * dws;
            }
        }
        t += dt;
    }

    // ---------- terminal costs + block reduction ----------
    if (is_h && q == 0) {
        float e1 = Y_lo - y_lo * y_lo;
        float e2 = D_lo - 2.f * y_lo;
        S->red[slo] = fmaf(e1, e1, fmaf(e2, e2, loss_lo));
        float f1 = Y_hi - y_hi * y_hi;
        float f2 = D_hi - 2.f * y_hi;
        S->red[slo + 4] = fmaf(f1, f1, fmaf(f2, f2, loss_hi));
    }
    __syncthreads();
    if (tid == 0) {
        float sum = 0.f;
#pragma unroll 8
        for (int i = 0; i < SAMP; i++) sum += S->red[i];
        g_partials[blockIdx.x] = sum;
    }
}

__global__ void reduce_kernel(float *out, int nblocks, float invB) {
    __shared__ float sh[256];
    float sum = 0.f;
    for (int i = threadIdx.x; i < nblocks; i += 256) sum += g_partials[i];
    sh[threadIdx.x] = sum;
    __syncthreads();
    for (int off = 128; off > 0; off >>= 1) {
        if (threadIdx.x < off) sh[threadIdx.x] += sh[threadIdx.x + off];
        __syncthreads();
    }
    if (threadIdx.x == 0) out[0] = sh[0] * invB;
}

extern "C" void kernel_launch(void* const* d_in, const int* in_sizes, int n_in,
                              void* d_out, int out_size) {
    const float *W0  = (const float *)d_in[0];
    const float *b0  = (const float *)d_in[1];
    const float *W1  = (const float *)d_in[2];
    const float *b1  = (const float *)d_in[3];
    const float *W2  = (const float *)d_in[4];
    const float *b2  = (const float *)d_in[5];
    const float *W3  = (const float *)d_in[6];
    const float *b3  = (const float *)d_in[7];
    const float *W4  = (const float *)d_in[8];
    const float *b4  = (const float *)d_in[9];
    const float *y0p = (const float *)d_in[10];
    const float *dW  = (const float *)d_in[11];

    const int B = in_sizes[11] / NSTEPS;
    const int nblocks = B / SAMP;

    cudaFuncSetAttribute(fbsnn_kernel,
                         cudaFuncAttributeMaxDynamicSharedMemorySize,
                         (int)sizeof(Smem));

    nop_kernel<<<1, 32>>>();
    fbsnn_kernel<<<nblocks, THREADS, sizeof(Smem)>>>(
        W0, b0, W1, b1, W2, b2, W3, b3, W4, b4, y0p, dW, B);
    nop_kernel<<<1, 32>>>();
    reduce_kernel<<<1, 256>>>((float *)d_out, nblocks, 1.0f / (float)B);
}

// round 5
// speedup vs baseline: 4.6643x; 1.1736x over previous
#include <cuda_runtime.h>
#include <cuda_fp16.h>
#include <cstdint>

#define NSTEPS  100
#define SAMP    64
#define THREADS 256
#define HID     64
#define MAXBLK  4096

// BL[l][wp][kt][ntp][lane] -> uint4 = (nt=2ntp: k-lo, k-hi ; nt=2ntp+1: k-lo, k-hi)
struct Smem {
    uint4 BL[3][2][4][4][32];             // 49152 B
    float w0t[HID], w0y[HID], b0v[HID];
    float bl[3][HID];
    float w4[HID];
    float red[SAMP];
    float b4v;
};

__device__ float g_partials[MAXBLK];

__device__ __forceinline__ void mma16816(float* d, const unsigned* a, const unsigned* b) {
    asm volatile(
        "mma.sync.aligned.m16n8k16.row.col.f32.f16.f16.f32 "
        "{%0,%1,%2,%3}, {%4,%5,%6,%7}, {%8,%9}, {%0,%1,%2,%3};"
        : "+f"(d[0]), "+f"(d[1]), "+f"(d[2]), "+f"(d[3])
        : "r"(a[0]), "r"(a[1]), "r"(a[2]), "r"(a[3]), "r"(b[0]), "r"(b[1]));
}
// fp16-accumulator variant (2x rate); used for the small correction terms
__device__ __forceinline__ void mma16816h(unsigned* c, const unsigned* a, const unsigned* b) {
    asm volatile(
        "mma.sync.aligned.m16n8k16.row.col.f16.f16.f16.f16 "
        "{%0,%1}, {%2,%3,%4,%5}, {%6,%7}, {%0,%1};"
        : "+r"(c[0]), "+r"(c[1])
        : "r"(a[0]), "r"(a[1]), "r"(a[2]), "r"(a[3]), "r"(b[0]), "r"(b[1]));
}

// split two fp32 values into (hi, lo) fp16 parts, packed as f16x2 (x -> low half)
__device__ __forceinline__ void split_pack(float x, float y,
                                           unsigned &u0, unsigned &u1) {
    __half2 p0 = __floats2half2_rn(x, y);
    float2 f = __half22float2(p0);
    __half2 p1 = __floats2half2_rn(x - f.x, y - f.y);
    u0 = *reinterpret_cast<unsigned*>(&p0);
    u1 = *reinterpret_cast<unsigned*>(&p1);
}

__global__ void nop_kernel() {}

__global__ void __launch_bounds__(THREADS, 2) fbsnn_kernel(
    const float *__restrict__ W0, const float *__restrict__ b0,
    const float *__restrict__ W1, const float *__restrict__ b1,
    const float *__restrict__ W2, const float *__restrict__ b2,
    const float *__restrict__ W3, const float *__restrict__ b3,
    const float *__restrict__ W4, const float *__restrict__ b4,
    const float *__restrict__ y0p, const float *__restrict__ dW, int B)
{
    extern __shared__ unsigned char smem_raw[];
    Smem *S = reinterpret_cast<Smem *>(smem_raw);

    const int tid  = threadIdx.x;
    const int wid  = tid >> 5;
    const int lane = tid & 31;
    const int g    = lane >> 2;       // fragment row group: rows g (h) and g+8 (v)
    const int q    = lane & 3;        // quad (col pair)

    // ---------------- one-time init: weight fragment tables ----------------
    {
        const float *Wl[3] = {W1, W2, W3};
        for (int idx = tid; idx < 3 * 2 * 4 * 4 * 32; idx += THREADS) {
            int ln  = idx & 31;
            int ntp = (idx >> 5) & 3;
            int kt  = (idx >> 7) & 3;
            int wp  = (idx >> 9) & 1;
            int l   = idx >> 10;
            int gg = ln >> 2, qq = ln & 3;
            unsigned v[4];
#pragma unroll
            for (int r = 0; r < 4; r++) {
                int nt  = 2 * ntp + (r >> 1);
                int reg = r & 1;
                int j   = nt * 8 + gg;               // output unit (N index)
                int k0  = kt * 16 + 2 * qq + 8 * reg;
                unsigned p0, p1;
                split_pack(Wl[l][j * HID + k0], Wl[l][j * HID + k0 + 1], p0, p1);
                v[r] = wp ? p1 : p0;
            }
            S->BL[l][wp][kt][ntp][ln] = make_uint4(v[0], v[1], v[2], v[3]);
        }
        for (int idx = tid; idx < HID; idx += THREADS) {
            S->w0t[idx] = W0[2 * idx];
            S->w0y[idx] = W0[2 * idx + 1];
            S->b0v[idx] = b0[idx];
            S->bl[0][idx] = b1[idx];
            S->bl[1][idx] = b2[idx];
            S->bl[2][idx] = b3[idx];
            S->w4[idx]  = W4[idx];
        }
        if (tid == 0) S->b4v = b4[0];
    }
    __syncthreads();   // the ONLY block barrier until the final reduction

    const float dt = 0.01f;
    const float sqrt_dt = sqrtf(0.01f);   // matches np.float32(0.01)**0.5

    // each lane fully owns one sample: rows g (h-chain) and g+8 (v-chain)
    const int  samp = 8 * wid + g;                 // block-local sample
    const long gsamp = (long)blockIdx.x * SAMP + samp;

    float y = y0p[0];
    float loss = 0.f, Ytil = 0.f, Y = 0.f, D = 0.f;
    float t = 0.f;

    for (int n = 0; n <= NSTEPS; n++) {
        // prefetch this step's noise; consumed after 4 layers of compute
        float dwn = (n < NSTEPS) ? dW[(long)n * B + gsamp] : 0.f;

        unsigned A0[4][4], A1[4][4];   // fp16x2 A fragments (hi / lo parts)

        // ---------- layer 0: build A fragments from (t, y) ----------
#pragma unroll
        for (int nt = 0; nt < 8; nt++) {
            float hh[2], vv[2];
#pragma unroll
            for (int e = 0; e < 2; e++) {
                const int j = nt * 8 + 2 * q + e;
                const float wy = S->w0y[j];
                float z = fmaf(S->w0t[j], t, fmaf(wy, y, S->b0v[j]));
                hh[e] = __sinf(z);
                vv[e] = __cosf(z) * wy;
            }
            const int kt = nt >> 1, base = (nt & 1) * 2;
            split_pack(hh[0], hh[1], A0[kt][base],     A1[kt][base]);
            split_pack(vv[0], vv[1], A0[kt][base + 1], A1[kt][base + 1]);
        }

        // ---------- hidden layers 1..3 ----------
#pragma unroll
        for (int l = 0; l < 3; l++) {
            float d[8][4];
            unsigned cf[8][2];
#pragma unroll
            for (int nt = 0; nt < 8; nt++) {
#pragma unroll
                for (int i = 0; i < 4; i++) d[nt][i] = 0.f;
                cf[nt][0] = 0u; cf[nt][1] = 0u;
            }

            const uint4 *bp0 = &S->BL[l][0][0][0][0];
            const uint4 *bp1 = &S->BL[l][1][0][0][0];
#pragma unroll
            for (int kt = 0; kt < 4; kt++) {
#pragma unroll
                for (int half = 0; half < 2; half++) {
                    // ntp = 2*half, 2*half+1 -> nt = 4*half .. 4*half+3
                    uint4 f0a = bp0[(kt * 4 + 2 * half) * 32 + lane];
                    uint4 f0b = bp0[(kt * 4 + 2 * half + 1) * 32 + lane];
                    uint4 f1a = bp1[(kt * 4 + 2 * half) * 32 + lane];
                    uint4 f1b = bp1[(kt * 4 + 2 * half + 1) * 32 + lane];
                    unsigned w0f[4][2] = {{f0a.x, f0a.y}, {f0a.z, f0a.w},
                                          {f0b.x, f0b.y}, {f0b.z, f0b.w}};
                    unsigned w1f[4][2] = {{f1a.x, f1a.y}, {f1a.z, f1a.w},
                                          {f1b.x, f1b.y}, {f1b.z, f1b.w}};
#pragma unroll
                    for (int i = 0; i < 4; i++) {
                        const int nt = 4 * half + i;
                        mma16816(d[nt], A0[kt], w0f[i]);       // main, f32 accum
                        mma16816h(cf[nt], A1[kt], w0f[i]);     // corr, f16 accum
                        mma16816h(cf[nt], A0[kt], w1f[i]);     // corr, f16 accum
                    }
                }
            }
            // merge fp16 correction accumulators into d
#pragma unroll
            for (int nt = 0; nt < 8; nt++) {
                float2 c0 = __half22float2(*reinterpret_cast<__half2*>(&cf[nt][0]));
                float2 c1 = __half22float2(*reinterpret_cast<__half2*>(&cf[nt][1]));
                d[nt][0] += c0.x; d[nt][1] += c0.y;
                d[nt][2] += c1.x; d[nt][3] += c1.y;
            }

            if (l < 2) {
                // epilogue: bias + sin/cos + fp16 split — fully lane-local
#pragma unroll
                for (int nt = 0; nt < 8; nt++) {
                    const int j0 = nt * 8 + 2 * q;
                    float z0 = d[nt][0] + S->bl[l][j0];
                    float z1 = d[nt][1] + S->bl[l][j0 + 1];
                    float h0 = __sinf(z0), h1 = __sinf(z1);
                    float v0 = __cosf(z0) * d[nt][2];
                    float v1 = __cosf(z1) * d[nt][3];
                    const int kt = nt >> 1, base = (nt & 1) * 2;
                    split_pack(h0, h1, A0[kt][base],     A1[kt][base]);
                    split_pack(v0, v1, A0[kt][base + 1], A1[kt][base + 1]);
                }
            } else {
                // final: activation + W4 dot-product, quad butterfly
                float Yp = 0.f, Dp = 0.f;
#pragma unroll
                for (int nt = 0; nt < 8; nt++) {
                    const int j0 = nt * 8 + 2 * q;
                    float z0 = d[nt][0] + S->bl[2][j0];
                    float z1 = d[nt][1] + S->bl[2][j0 + 1];
                    const float w40 = S->w4[j0], w41 = S->w4[j0 + 1];
                    Yp = fmaf(w40, __sinf(z0), Yp);
                    Yp = fmaf(w41, __sinf(z1), Yp);
                    Dp = fmaf(w40 * __cosf(z0), d[nt][2], Dp);
                    Dp = fmaf(w41 * __cosf(z1), d[nt][3], Dp);
                }
                Yp += __shfl_xor_sync(0xffffffffu, Yp, 1);
                Yp += __shfl_xor_sync(0xffffffffu, Yp, 2);
                Dp += __shfl_xor_sync(0xffffffffu, Dp, 1);
                Dp += __shfl_xor_sync(0xffffffffu, Dp, 2);
                Y = S->b4v + Yp;
                D = Dp;
            }
        }

        // ---------- Euler-Maruyama step (per-lane, register resident) ----------
        if (n > 0) {
            float dd = Y - Ytil;
            loss = fmaf(dd, dd, loss);
        }
        if (n < NSTEPS) {
            float Z0 = 0.5f * D, q0 = -D;
            float dws = dwn * sqrt_dt;
            y = y + q0 * dt + 0.5f * dws;
            Ytil = Y - (q0 * q0) * dt + Z0 * dws;
        }
        t += dt;
    }

    // ---------- terminal costs + block reduction ----------
    if (q == 0) {
        float e1 = Y - y * y;
        float e2 = D - 2.f * y;
        S->red[samp] = fmaf(e1, e1, fmaf(e2, e2, loss));
    }
    __syncthreads();
    if (tid == 0) {
        float sum = 0.f;
#pragma unroll 8
        for (int i = 0; i < SAMP; i++) sum += S->red[i];
        g_partials[blockIdx.x] = sum;
    }
}

__global__ void reduce_kernel(float *out, int nblocks, float invB) {
    __shared__ float sh[256];
    float sum = 0.f;
    for (int i = threadIdx.x; i < nblocks; i += 256) sum += g_partials[i];
    sh[threadIdx.x] = sum;
    __syncthreads();
    for (int off = 128; off > 0; off >>= 1) {
        if (threadIdx.x < off) sh[threadIdx.x] += sh[threadIdx.x + off];
        __syncthreads();
    }
    if (threadIdx.x == 0) out[0] = sh[0] * invB;
}

extern "C" void kernel_launch(void* const* d_in, const int* in_sizes, int n_in,
                              void* d_out, int out_size) {
    const float *W0  = (const float *)d_in[0];
    const float *b0  = (const float *)d_in[1];
    const float *W1  = (const float *)d_in[2];
    const float *b1  = (const float *)d_in[3];
    const float *W2  = (const float *)d_in[4];
    const float *b2  = (const float *)d_in[5];
    const float *W3  = (const float *)d_in[6];
    const float *b3  = (const float *)d_in[7];
    const float *W4  = (const float *)d_in[8];
    const float *b4  = (const float *)d_in[9];
    const float *y0p = (const float *)d_in[10];
    const float *dW  = (const float *)d_in[11];

    const int B = in_sizes[11] / NSTEPS;
    const int nblocks = B / SAMP;

    cudaFuncSetAttribute(fbsnn_kernel,
                         cudaFuncAttributeMaxDynamicSharedMemorySize,
                         (int)sizeof(Smem));

    nop_kernel<<<1, 32>>>();
    fbsnn_kernel<<<nblocks, THREADS, sizeof(Smem)>>>(
        W0, b0, W1, b1, W2, b2, W3, b3, W4, b4, y0p, dW, B);
    nop_kernel<<<1, 32>>>();
    reduce_kernel<<<1, 256>>>((float *)d_out, nblocks, 1.0f / (float)B);
}

// round 6
// speedup vs baseline: 4.7932x; 1.0276x over previous
#include <cuda_runtime.h>
#include <cuda_fp16.h>
#include <cstdint>

#define NSTEPS  100
#define SAMP    64
#define THREADS 256
#define HID     64
#define MAXBLK  4096

// BL[l][wp][kt][ntp][lane] -> uint4 = (nt=2ntp: k-lo, k-hi ; nt=2ntp+1: k-lo, k-hi)
struct Smem {
    uint4 BL[3][2][4][4][32];             // 49152 B
    float c0[NSTEPS + 1][HID];            // w0t[j]*t_n + b0[j], exact t accumulation
    float w0y[HID];
    float bl[3][HID];
    float w4[HID];
    float red[SAMP];
    float b4v;
};

__device__ float g_partials[MAXBLK];

__device__ __forceinline__ void mma16816(float* d, const unsigned* a, const unsigned* b) {
    asm volatile(
        "mma.sync.aligned.m16n8k16.row.col.f32.f16.f16.f32 "
        "{%0,%1,%2,%3}, {%4,%5,%6,%7}, {%8,%9}, {%0,%1,%2,%3};"
        : "+f"(d[0]), "+f"(d[1]), "+f"(d[2]), "+f"(d[3])
        : "r"(a[0]), "r"(a[1]), "r"(a[2]), "r"(a[3]), "r"(b[0]), "r"(b[1]));
}
// fp16-accumulator variant (2x rate); used for the small correction terms
__device__ __forceinline__ void mma16816h(unsigned* c, const unsigned* a, const unsigned* b) {
    asm volatile(
        "mma.sync.aligned.m16n8k16.row.col.f16.f16.f16.f16 "
        "{%0,%1}, {%2,%3,%4,%5}, {%6,%7}, {%0,%1};"
        : "+r"(c[0]), "+r"(c[1])
        : "r"(a[0]), "r"(a[1]), "r"(a[2]), "r"(a[3]), "r"(b[0]), "r"(b[1]));
}

// split two fp32 values into (hi, lo) fp16 parts, packed as f16x2 (x -> low half)
__device__ __forceinline__ void split_pack(float x, float y,
                                           unsigned &u0, unsigned &u1) {
    __half2 p0 = __floats2half2_rn(x, y);
    float2 f = __half22float2(p0);
    __half2 p1 = __floats2half2_rn(x - f.x, y - f.y);
    u0 = *reinterpret_cast<unsigned*>(&p0);
    u1 = *reinterpret_cast<unsigned*>(&p1);
}

__global__ void nop_kernel() {}

__global__ void __launch_bounds__(THREADS, 2) fbsnn_kernel(
    const float *__restrict__ W0, const float *__restrict__ b0,
    const float *__restrict__ W1, const float *__restrict__ b1,
    const float *__restrict__ W2, const float *__restrict__ b2,
    const float *__restrict__ W3, const float *__restrict__ b3,
    const float *__restrict__ W4, const float *__restrict__ b4,
    const float *__restrict__ y0p, const float *__restrict__ dW, int B)
{
    extern __shared__ unsigned char smem_raw[];
    Smem *S = reinterpret_cast<Smem *>(smem_raw);

    const int tid  = threadIdx.x;
    const int wid  = tid >> 5;
    const int lane = tid & 31;
    const int g    = lane >> 2;       // fragment row group: rows g (h) and g+8 (v)
    const int q    = lane & 3;        // quad (col pair)

    // ---------------- one-time init ----------------
    {
        const float *Wl[3] = {W1, W2, W3};
        for (int idx = tid; idx < 3 * 2 * 4 * 4 * 32; idx += THREADS) {
            int ln  = idx & 31;
            int ntp = (idx >> 5) & 3;
            int kt  = (idx >> 7) & 3;
            int wp  = (idx >> 9) & 1;
            int l   = idx >> 10;
            int gg = ln >> 2, qq = ln & 3;
            unsigned v[4];
#pragma unroll
            for (int r = 0; r < 4; r++) {
                int nt  = 2 * ntp + (r >> 1);
                int reg = r & 1;
                int j   = nt * 8 + gg;               // output unit (N index)
                int k0  = kt * 16 + 2 * qq + 8 * reg;
                unsigned p0, p1;
                split_pack(Wl[l][j * HID + k0], Wl[l][j * HID + k0 + 1], p0, p1);
                v[r] = wp ? p1 : p0;
            }
            S->BL[l][wp][kt][ntp][ln] = make_uint4(v[0], v[1], v[2], v[3]);
        }
        for (int idx = tid; idx < HID; idx += THREADS) {
            S->w0y[idx] = W0[2 * idx + 1];
            S->bl[0][idx] = b1[idx];
            S->bl[1][idx] = b2[idx];
            S->bl[2][idx] = b3[idx];
            S->w4[idx]  = W4[idx];
        }
        // t-part of layer 0, with the reference's exact iterative t accumulation
        if (tid < HID) {
            const float w0tj = W0[2 * tid];
            const float b0j  = b0[tid];
            float tt = 0.f;
            for (int n = 0; n <= NSTEPS; n++) {
                S->c0[n][tid] = fmaf(w0tj, tt, b0j);
                tt += 0.01f;
            }
        }
        if (tid == 0) S->b4v = b4[0];
    }
    __syncthreads();   // the ONLY block barrier until the final reduction

    const float dt = 0.01f;
    const float sqrt_dt = sqrtf(0.01f);   // matches np.float32(0.01)**0.5

    // each lane fully owns one sample: rows g (h-chain) and g+8 (v-chain)
    const int  samp = 8 * wid + g;                 // block-local sample
    const long gsamp = (long)blockIdx.x * SAMP + samp;

    float y = y0p[0];
    float loss = 0.f, Ytil = 0.f, Y = 0.f, D = 0.f;

    for (int n = 0; n <= NSTEPS; n++) {
        // prefetch this step's noise; consumed after 4 layers of compute
        float dwn = (n < NSTEPS) ? __ldcs(&dW[(long)n * B + gsamp]) : 0.f;

        unsigned A0[4][4], A1[4][4];   // fp16x2 A fragments (hi / lo parts)

        // ---------- layer 0: z = w0y*y + c0[n][j]  (t-part precomputed) ----------
        {
            const float *cn = &S->c0[n][0];
#pragma unroll
            for (int nt = 0; nt < 8; nt++) {
                float hh[2], vv[2];
#pragma unroll
                for (int e = 0; e < 2; e++) {
                    const int j = nt * 8 + 2 * q + e;
                    const float wy = S->w0y[j];
                    float z = fmaf(wy, y, cn[j]);
                    hh[e] = __sinf(z);
                    vv[e] = __cosf(z) * wy;
                }
                const int kt = nt >> 1, base = (nt & 1) * 2;
                split_pack(hh[0], hh[1], A0[kt][base],     A1[kt][base]);
                split_pack(vv[0], vv[1], A0[kt][base + 1], A1[kt][base + 1]);
            }
        }

        // ---------- hidden layers 1..3 ----------
#pragma unroll
        for (int l = 0; l < 3; l++) {
            float d[8][4];
            unsigned cf[8][2];
#pragma unroll
            for (int nt = 0; nt < 8; nt++) {
                // bias folded into the accumulator init (h-rows only)
                const int j0 = nt * 8 + 2 * q;
                d[nt][0] = S->bl[l][j0];
                d[nt][1] = S->bl[l][j0 + 1];
                d[nt][2] = 0.f;
                d[nt][3] = 0.f;
                cf[nt][0] = 0u; cf[nt][1] = 0u;
            }

            const uint4 *bp0 = &S->BL[l][0][0][0][0];
            const uint4 *bp1 = &S->BL[l][1][0][0][0];
#pragma unroll
            for (int kt = 0; kt < 4; kt++) {
#pragma unroll
                for (int half = 0; half < 2; half++) {
                    uint4 f0a = bp0[(kt * 4 + 2 * half) * 32 + lane];
                    uint4 f0b = bp0[(kt * 4 + 2 * half + 1) * 32 + lane];
                    uint4 f1a = bp1[(kt * 4 + 2 * half) * 32 + lane];
                    uint4 f1b = bp1[(kt * 4 + 2 * half + 1) * 32 + lane];
                    unsigned w0f[4][2] = {{f0a.x, f0a.y}, {f0a.z, f0a.w},
                                          {f0b.x, f0b.y}, {f0b.z, f0b.w}};
                    unsigned w1f[4][2] = {{f1a.x, f1a.y}, {f1a.z, f1a.w},
                                          {f1b.x, f1b.y}, {f1b.z, f1b.w}};
#pragma unroll
                    for (int i = 0; i < 4; i++) {
                        const int nt = 4 * half + i;
                        mma16816(d[nt], A0[kt], w0f[i]);       // main, f32 accum
                        mma16816h(cf[nt], A1[kt], w0f[i]);     // corr, f16 accum
                        mma16816h(cf[nt], A0[kt], w1f[i]);     // corr, f16 accum
                    }
                }
            }

            if (l < 2) {
                // epilogue: corr-merge + sin/cos + fp16 split — fully lane-local
#pragma unroll
                for (int nt = 0; nt < 8; nt++) {
                    float2 c0 = __half22float2(*reinterpret_cast<__half2*>(&cf[nt][0]));
                    float2 c1 = __half22float2(*reinterpret_cast<__half2*>(&cf[nt][1]));
                    float z0 = d[nt][0] + c0.x;
                    float z1 = d[nt][1] + c0.y;
                    float u0 = d[nt][2] + c1.x;
                    float u1 = d[nt][3] + c1.y;
                    float h0 = __sinf(z0), h1 = __sinf(z1);
                    float v0 = __cosf(z0) * u0;
                    float v1 = __cosf(z1) * u1;
                    const int kt = nt >> 1, base = (nt & 1) * 2;
                    split_pack(h0, h1, A0[kt][base],     A1[kt][base]);
                    split_pack(v0, v1, A0[kt][base + 1], A1[kt][base + 1]);
                }
            } else {
                // final: activation + W4 dot-product, quad butterfly
                float Yp = 0.f, Dp = 0.f;
#pragma unroll
                for (int nt = 0; nt < 8; nt++) {
                    float2 c0 = __half22float2(*reinterpret_cast<__half2*>(&cf[nt][0]));
                    float2 c1 = __half22float2(*reinterpret_cast<__half2*>(&cf[nt][1]));
                    const int j0 = nt * 8 + 2 * q;
                    float z0 = d[nt][0] + c0.x;
                    float z1 = d[nt][1] + c0.y;
                    float u0 = d[nt][2] + c1.x;
                    float u1 = d[nt][3] + c1.y;
                    const float w40 = S->w4[j0], w41 = S->w4[j0 + 1];
                    Yp = fmaf(w40, __sinf(z0), Yp);
                    Yp = fmaf(w41, __sinf(z1), Yp);
                    Dp = fmaf(w40 * __cosf(z0), u0, Dp);
                    Dp = fmaf(w41 * __cosf(z1), u1, Dp);
                }
                Yp += __shfl_xor_sync(0xffffffffu, Yp, 1);
                Yp += __shfl_xor_sync(0xffffffffu, Yp, 2);
                Dp += __shfl_xor_sync(0xffffffffu, Dp, 1);
                Dp += __shfl_xor_sync(0xffffffffu, Dp, 2);
                Y = S->b4v + Yp;
                D = Dp;
            }
        }

        // ---------- Euler-Maruyama step (per-lane, register resident) ----------
        if (n > 0) {
            float dd = Y - Ytil;
            loss = fmaf(dd, dd, loss);
        }
        if (n < NSTEPS) {
            float Z0 = 0.5f * D, q0 = -D;
            float dws = dwn * sqrt_dt;
            y = y + q0 * dt + 0.5f * dws;
            Ytil = Y - (q0 * q0) * dt + Z0 * dws;
        }
    }

    // ---------- terminal costs + block reduction ----------
    if (q == 0) {
        float e1 = Y - y * y;
        float e2 = D - 2.f * y;
        S->red[samp] = fmaf(e1, e1, fmaf(e2, e2, loss));
    }
    __syncthreads();
    if (tid == 0) {
        float sum = 0.f;
#pragma unroll 8
        for (int i = 0; i < SAMP; i++) sum += S->red[i];
        g_partials[blockIdx.x] = sum;
    }
}

__global__ void reduce_kernel(float *out, int nblocks, float invB) {
    __shared__ float sh[256];
    float sum = 0.f;
    for (int i = threadIdx.x; i < nblocks; i += 256) sum += g_partials[i];
    sh[threadIdx.x] = sum;
    __syncthreads();
    for (int off = 128; off > 0; off >>= 1) {
        if (threadIdx.x < off) sh[threadIdx.x] += sh[threadIdx.x + off];
        __syncthreads();
    }
    if (threadIdx.x == 0) out[0] = sh[0] * invB;
}

extern "C" void kernel_launch(void* const* d_in, const int* in_sizes, int n_in,
                              void* d_out, int out_size) {
    const float *W0  = (const float *)d_in[0];
    const float *b0  = (const float *)d_in[1];
    const float *W1  = (const float *)d_in[2];
    const float *b1  = (const float *)d_in[3];
    const float *W2  = (const float *)d_in[4];
    const float *b2  = (const float *)d_in[5];
    const float *W3  = (const float *)d_in[6];
    const float *b3  = (const float *)d_in[7];
    const float *W4  = (const float *)d_in[8];
    const float *b4  = (const float *)d_in[9];
    const float *y0p = (const float *)d_in[10];
    const float *dW  = (const float *)d_in[11];

    const int B = in_sizes[11] / NSTEPS;
    const int nblocks = B / SAMP;

    cudaFuncSetAttribute(fbsnn_kernel,
                         cudaFuncAttributeMaxDynamicSharedMemorySize,
                         (int)sizeof(Smem));

    nop_kernel<<<1, 32>>>();
    fbsnn_kernel<<<nblocks, THREADS, sizeof(Smem)>>>(
        W0, b0, W1, b1, W2, b2, W3, b3, W4, b4, y0p, dW, B);
    nop_kernel<<<1, 32>>>();
    reduce_kernel<<<1, 256>>>((float *)d_out, nblocks, 1.0f / (float)B);
}